// round 10
// baseline (speedup 1.0000x reference)
#include <cuda_runtime.h>

#define RBLOCKS 888            // 148 SMs * 6 blocks, exactly one wave
#define RTHREADS 256

// Per-block partial sums: layout [accumulator][block].
__device__ float g_part[3 * RBLOCKS];
__device__ unsigned int g_ticket;   // zero-init; last block resets to 0

// Per-row fused math. Accumulates:
//   s0 += dmean^2 + dr^2              (eval MSE, scaled later by w0/B; note 2x folded)
//   sx += (p.vhx - t.vhx)^2           (weighted by w1+w4)
//   sy += (p.vhy - t.vhy)^2           (weighted by w2+w3)
__device__ __forceinline__ void accum_row(float pa, float pb, float pd,
                                          float ta, float tb, float td,
                                          float& s0, float& sx, float& sy) {
    // pred tensor
    float psum  = pa + pd;
    float pdiff = 0.5f * (pa - pd);
    float pb2   = pb * pb;
    float pr2   = fmaf(pdiff, pdiff, pb2);
    float pr    = (pr2 > 0.0f) ? pr2 * rsqrtf(pr2) : 0.0f;   // sqrt via MUFU.RSQ
    float pvy   = pr - pdiff;                                // lam_hi - a
    float pn2   = fmaf(pvy, pvy, pb2);
    bool  ps    = (pn2 > 1e-37f);
    float pinv  = rsqrtf(pn2);
    float pvhx  = ps ? pb  * pinv : 1.0f;
    float pvhy  = ps ? pvy * pinv : 0.0f;
    // true tensor
    float tsum  = ta + td;
    float tdiff = 0.5f * (ta - td);
    float tb2   = tb * tb;
    float tr2   = fmaf(tdiff, tdiff, tb2);
    float tr    = (tr2 > 0.0f) ? tr2 * rsqrtf(tr2) : 0.0f;
    float tvy   = tr - tdiff;
    float tn2   = fmaf(tvy, tvy, tb2);
    bool  ts    = (tn2 > 1e-37f);
    float tinv  = rsqrtf(tn2);
    float tvhx  = ts ? tb  * tinv : 1.0f;
    float tvhy  = ts ? tvy * tinv : 0.0f;
    // accumulate
    float dmean = 0.5f * (psum - tsum);
    float dr    = pr - tr;
    s0 = fmaf(dmean, dmean, s0);
    s0 = fmaf(dr, dr, s0);
    float dx = pvhx - tvhx;
    float dy = pvhy - tvhy;
    sx = fmaf(dx, dx, sx);
    sy = fmaf(dy, dy, sy);
}

__global__ __launch_bounds__(RTHREADS, 6)
void eigh_fused_kernel(const float4* __restrict__ pred4,
                       const float4* __restrict__ true4,
                       const float*  __restrict__ pred,
                       const float*  __restrict__ tru,
                       const float*  __restrict__ w,
                       float* __restrict__ out,
                       int ngroups, int B) {
    float s0 = 0.f, sx = 0.f, sy = 0.f;

    int tid = threadIdx.x;
    int stride = gridDim.x * blockDim.x;
    for (int g = blockIdx.x * blockDim.x + tid; g < ngroups; g += stride) {
        // 4 rows = 12 floats = 3x float4, coalesced LDG.128
        float4 p0 = pred4[3 * g + 0];
        float4 p1 = pred4[3 * g + 1];
        float4 p2 = pred4[3 * g + 2];
        float4 t0 = true4[3 * g + 0];
        float4 t1 = true4[3 * g + 1];
        float4 t2 = true4[3 * g + 2];
        accum_row(p0.x, p0.y, p0.z,  t0.x, t0.y, t0.z,  s0, sx, sy);
        accum_row(p0.w, p1.x, p1.y,  t0.w, t1.x, t1.y,  s0, sx, sy);
        accum_row(p1.z, p1.w, p2.x,  t1.z, t1.w, t2.x,  s0, sx, sy);
        accum_row(p2.y, p2.z, p2.w,  t2.y, t2.z, t2.w,  s0, sx, sy);
    }

    // Tail rows (B % 4), block 0 scalar path
    int tail = B - 4 * ngroups;
    if (blockIdx.x == 0 && tid < tail) {
        int r = 4 * ngroups + tid;
        accum_row(pred[3 * r], pred[3 * r + 1], pred[3 * r + 2],
                  tru [3 * r], tru [3 * r + 1], tru [3 * r + 2],
                  s0, sx, sy);
    }

    // Deterministic block reduction.
    __shared__ float sm[3][RTHREADS / 32];
    int lane = tid & 31;
    int warp = tid >> 5;
    #pragma unroll
    for (int off = 16; off > 0; off >>= 1) {
        s0 += __shfl_down_sync(0xffffffffu, s0, off);
        sx += __shfl_down_sync(0xffffffffu, sx, off);
        sy += __shfl_down_sync(0xffffffffu, sy, off);
    }
    if (lane == 0) {
        sm[0][warp] = s0; sm[1][warp] = sx; sm[2][warp] = sy;
    }
    __syncthreads();
    __shared__ bool s_last;
    if (warp == 0) {
        const int nw = RTHREADS / 32;
        float v0 = (lane < nw) ? sm[0][lane] : 0.f;
        float v1 = (lane < nw) ? sm[1][lane] : 0.f;
        float v2 = (lane < nw) ? sm[2][lane] : 0.f;
        #pragma unroll
        for (int off = nw / 2; off > 0; off >>= 1) {
            v0 += __shfl_down_sync(0xffffffffu, v0, off);
            v1 += __shfl_down_sync(0xffffffffu, v1, off);
            v2 += __shfl_down_sync(0xffffffffu, v2, off);
        }
        if (lane == 0) {
            g_part[0 * RBLOCKS + blockIdx.x] = v0;
            g_part[1 * RBLOCKS + blockIdx.x] = v1;
            g_part[2 * RBLOCKS + blockIdx.x] = v2;
            __threadfence();
            unsigned int t = atomicAdd(&g_ticket, 1u);
            s_last = (t == (unsigned int)(gridDim.x - 1));
        }
    }
    __syncthreads();

    // Last arriving block reduces partials (fixed order -> deterministic).
    if (s_last) {
        __shared__ double dsm[3];
        if (warp < 3) {
            double s = 0.0;
            for (int i = lane; i < RBLOCKS; i += 32)
                s += (double)__ldcg(&g_part[warp * RBLOCKS + i]);
            #pragma unroll
            for (int off = 16; off > 0; off >>= 1)
                s += __shfl_down_sync(0xffffffffu, s, off);
            if (lane == 0) dsm[warp] = s;
        }
        __syncthreads();
        if (tid == 0) {
            double Bd = (double)B;
            // evals_mse: sum over 2B entries of (de)^2 = 2*(dmean^2+dr^2) summed
            //            over B rows -> w0 * 2*S0 / (2B) = w0 * S0 / B.
            // evec terms: dv2x = -dv1y, dv2y = dv1x ->
            //            (w1+w4)*Sx/B + (w2+w3)*Sy/B.
            double mse = (double)w[0] * dsm[0] / Bd
                       + ((double)w[1] + (double)w[4]) * dsm[1] / Bd
                       + ((double)w[2] + (double)w[3]) * dsm[2] / Bd;
            out[0] = (float)mse;
            g_ticket = 0;   // reset for next graph replay
        }
    }
}

extern "C" void kernel_launch(void* const* d_in, const int* in_sizes, int n_in,
                              void* d_out, int out_size) {
    const float* pred = (const float*)d_in[0];
    const float* tru  = (const float*)d_in[1];
    const float* w    = (const float*)d_in[2];
    float* out = (float*)d_out;

    int B = in_sizes[0] / 3;
    int ngroups = B / 4;

    eigh_fused_kernel<<<RBLOCKS, RTHREADS>>>(
        (const float4*)pred, (const float4*)tru, pred, tru, w, out, ngroups, B);
}

// round 11
// speedup vs baseline: 1.0286x; 1.0286x over previous
#include <cuda_runtime.h>

#define RBLOCKS 888            // 148 SMs * 6 blocks, exactly one wave
#define RTHREADS 256

// Per-block partial sums: layout [accumulator][block].
__device__ float g_part[3 * RBLOCKS];
__device__ unsigned int g_ticket;   // zero-init; last block resets to 0

// Per-row fused math. Accumulates:
//   s0 += dmean^2 + dr^2              (eval MSE, scaled later by w0/B; note 2x folded)
//   sx += (p.vhx - t.vhx)^2           (weighted by w1+w4)
//   sy += (p.vhy - t.vhy)^2           (weighted by w2+w3)
__device__ __forceinline__ void accum_row(float pa, float pb, float pd,
                                          float ta, float tb, float td,
                                          float& s0, float& sx, float& sy) {
    // pred tensor
    float psum  = pa + pd;
    float pdiff = 0.5f * (pa - pd);
    float pb2   = pb * pb;
    float pr2   = fmaf(pdiff, pdiff, pb2);
    float pr    = (pr2 > 0.0f) ? pr2 * rsqrtf(pr2) : 0.0f;   // sqrt via MUFU.RSQ
    float pvy   = pr - pdiff;                                // lam_hi - a
    float pn2   = fmaf(pvy, pvy, pb2);
    bool  ps    = (pn2 > 1e-37f);
    float pinv  = rsqrtf(pn2);
    float pvhx  = ps ? pb  * pinv : 1.0f;
    float pvhy  = ps ? pvy * pinv : 0.0f;
    // true tensor
    float tsum  = ta + td;
    float tdiff = 0.5f * (ta - td);
    float tb2   = tb * tb;
    float tr2   = fmaf(tdiff, tdiff, tb2);
    float tr    = (tr2 > 0.0f) ? tr2 * rsqrtf(tr2) : 0.0f;
    float tvy   = tr - tdiff;
    float tn2   = fmaf(tvy, tvy, tb2);
    bool  ts    = (tn2 > 1e-37f);
    float tinv  = rsqrtf(tn2);
    float tvhx  = ts ? tb  * tinv : 1.0f;
    float tvhy  = ts ? tvy * tinv : 0.0f;
    // accumulate
    float dmean = 0.5f * (psum - tsum);
    float dr    = pr - tr;
    s0 = fmaf(dmean, dmean, s0);
    s0 = fmaf(dr, dr, s0);
    float dx = pvhx - tvhx;
    float dy = pvhy - tvhy;
    sx = fmaf(dx, dx, sx);
    sy = fmaf(dy, dy, sy);
}

__global__ __launch_bounds__(RTHREADS, 6)
void eigh_fused_kernel(const float4* __restrict__ pred4,
                       const float4* __restrict__ true4,
                       const float*  __restrict__ pred,
                       const float*  __restrict__ tru,
                       const float*  __restrict__ w,
                       float* __restrict__ out,
                       int ngroups, int B) {
    float s0 = 0.f, sx = 0.f, sy = 0.f;

    int tid = threadIdx.x;
    int stride = gridDim.x * blockDim.x;
    for (int g = blockIdx.x * blockDim.x + tid; g < ngroups; g += stride) {
        // 4 rows = 12 floats = 3x float4, coalesced LDG.128
        float4 p0 = pred4[3 * g + 0];
        float4 p1 = pred4[3 * g + 1];
        float4 p2 = pred4[3 * g + 2];
        float4 t0 = true4[3 * g + 0];
        float4 t1 = true4[3 * g + 1];
        float4 t2 = true4[3 * g + 2];
        accum_row(p0.x, p0.y, p0.z,  t0.x, t0.y, t0.z,  s0, sx, sy);
        accum_row(p0.w, p1.x, p1.y,  t0.w, t1.x, t1.y,  s0, sx, sy);
        accum_row(p1.z, p1.w, p2.x,  t1.z, t1.w, t2.x,  s0, sx, sy);
        accum_row(p2.y, p2.z, p2.w,  t2.y, t2.z, t2.w,  s0, sx, sy);
    }

    // Tail rows (B % 4), block 0 scalar path
    int tail = B - 4 * ngroups;
    if (blockIdx.x == 0 && tid < tail) {
        int r = 4 * ngroups + tid;
        accum_row(pred[3 * r], pred[3 * r + 1], pred[3 * r + 2],
                  tru [3 * r], tru [3 * r + 1], tru [3 * r + 2],
                  s0, sx, sy);
    }

    // Deterministic block reduction.
    __shared__ float sm[3][RTHREADS / 32];
    int lane = tid & 31;
    int warp = tid >> 5;
    #pragma unroll
    for (int off = 16; off > 0; off >>= 1) {
        s0 += __shfl_down_sync(0xffffffffu, s0, off);
        sx += __shfl_down_sync(0xffffffffu, sx, off);
        sy += __shfl_down_sync(0xffffffffu, sy, off);
    }
    if (lane == 0) {
        sm[0][warp] = s0; sm[1][warp] = sx; sm[2][warp] = sy;
    }
    __syncthreads();
    __shared__ bool s_last;
    if (warp == 0) {
        const int nw = RTHREADS / 32;
        float v0 = (lane < nw) ? sm[0][lane] : 0.f;
        float v1 = (lane < nw) ? sm[1][lane] : 0.f;
        float v2 = (lane < nw) ? sm[2][lane] : 0.f;
        #pragma unroll
        for (int off = nw / 2; off > 0; off >>= 1) {
            v0 += __shfl_down_sync(0xffffffffu, v0, off);
            v1 += __shfl_down_sync(0xffffffffu, v1, off);
            v2 += __shfl_down_sync(0xffffffffu, v2, off);
        }
        if (lane == 0) {
            g_part[0 * RBLOCKS + blockIdx.x] = v0;
            g_part[1 * RBLOCKS + blockIdx.x] = v1;
            g_part[2 * RBLOCKS + blockIdx.x] = v2;
            __threadfence();
            unsigned int t = atomicAdd(&g_ticket, 1u);
            s_last = (t == (unsigned int)(gridDim.x - 1));
        }
    }
    __syncthreads();

    // Last arriving block reduces partials (fixed order -> deterministic).
    if (s_last) {
        __shared__ double dsm[3];
        if (warp < 3) {
            double s = 0.0;
            for (int i = lane; i < RBLOCKS; i += 32)
                s += (double)__ldcg(&g_part[warp * RBLOCKS + i]);
            #pragma unroll
            for (int off = 16; off > 0; off >>= 1)
                s += __shfl_down_sync(0xffffffffu, s, off);
            if (lane == 0) dsm[warp] = s;
        }
        __syncthreads();
        if (tid == 0) {
            double Bd = (double)B;
            // evals_mse: sum over 2B entries of (de)^2 = 2*(dmean^2+dr^2) summed
            //            over B rows -> w0 * 2*S0 / (2B) = w0 * S0 / B.
            // evec terms: dv2x = -dv1y, dv2y = dv1x ->
            //            (w1+w4)*Sx/B + (w2+w3)*Sy/B.
            double mse = (double)w[0] * dsm[0] / Bd
                       + ((double)w[1] + (double)w[4]) * dsm[1] / Bd
                       + ((double)w[2] + (double)w[3]) * dsm[2] / Bd;
            out[0] = (float)mse;
            g_ticket = 0;   // reset for next graph replay
        }
    }
}

extern "C" void kernel_launch(void* const* d_in, const int* in_sizes, int n_in,
                              void* d_out, int out_size) {
    const float* pred = (const float*)d_in[0];
    const float* tru  = (const float*)d_in[1];
    const float* w    = (const float*)d_in[2];
    float* out = (float*)d_out;

    int B = in_sizes[0] / 3;
    int ngroups = B / 4;

    eigh_fused_kernel<<<RBLOCKS, RTHREADS>>>(
        (const float4*)pred, (const float4*)tru, pred, tru, w, out, ngroups, B);
}